// round 3
// baseline (speedup 1.0000x reference)
#include <cuda_runtime.h>

#define BB 4
#define CC 256
#define HH 56
#define WW 56
#define CR 64          // C / 4
#define GG 16          // groups
#define GC 16
#define KK 7
#define K2T 49
#define M2 (GG * K2T)  // 784
#define HW (HH * WW)   // 3136
#define PAD 3

// Scratch (__device__ globals; no allocations allowed)
__device__ float g_w1[BB * CR * HW];        // [B, Cr, HW]
__device__ float g_w2[BB * M2 * HW];        // [B, G*49, HW]

// ---------------------------------------------------------------------------
// K1: w1 = relu(bn(conv1_1x1(x))).  GEMM [64 x 256] x [256 x 3136] per batch.
// Tile 64o x 32px, 256 threads, 4x2 per thread, k-step 64, transposed A smem.
// Grid: 98 px-tiles x 4 batches = 392 blocks.
// ---------------------------------------------------------------------------
__global__ __launch_bounds__(256) void k1_conv1_bn_relu(
        const float* __restrict__ x,
        const float* __restrict__ w1w,
        const float* __restrict__ gamma,
        const float* __restrict__ beta,
        const float* __restrict__ mean,
        const float* __restrict__ var) {
    __shared__ float As[64 * 68];    // [k][o], pad 4 (stride 68 keeps 16B align)
    __shared__ float Bs[64 * 32];    // [k][px]

    const int tid = threadIdx.x;
    const int tx = tid & 15;         // px pair
    const int ty = tid >> 4;         // o quad
    const int px0 = blockIdx.x * 32; // 98*32 = 3136 exact, no guards
    const int b = blockIdx.y;

    float acc[4][2];
#pragma unroll
    for (int i = 0; i < 4; ++i) { acc[i][0] = 0.f; acc[i][1] = 0.f; }

    for (int kt = 0; kt < CC; kt += 64) {
#pragma unroll
        for (int r = 0; r < 16; ++r) {
            int idx = tid + r * 256;
            int o = idx >> 6, k = idx & 63;
            As[k * 68 + o] = w1w[o * CC + kt + k];
        }
#pragma unroll
        for (int r = 0; r < 8; ++r) {
            int idx = tid + r * 256;
            int k = idx >> 5, j = idx & 31;
            Bs[k * 32 + j] = x[(size_t)(b * CC + kt + k) * HW + px0 + j];
        }
        __syncthreads();

#pragma unroll 16
        for (int k = 0; k < 64; ++k) {
            float4 av = *(const float4*)&As[k * 68 + ty * 4];
            float2 bv = *(const float2*)&Bs[k * 32 + tx * 2];
            acc[0][0] = fmaf(av.x, bv.x, acc[0][0]);
            acc[0][1] = fmaf(av.x, bv.y, acc[0][1]);
            acc[1][0] = fmaf(av.y, bv.x, acc[1][0]);
            acc[1][1] = fmaf(av.y, bv.y, acc[1][1]);
            acc[2][0] = fmaf(av.z, bv.x, acc[2][0]);
            acc[2][1] = fmaf(av.z, bv.y, acc[2][1]);
            acc[3][0] = fmaf(av.w, bv.x, acc[3][0]);
            acc[3][1] = fmaf(av.w, bv.y, acc[3][1]);
        }
        __syncthreads();
    }

#pragma unroll
    for (int i = 0; i < 4; ++i) {
        int o = ty * 4 + i;
        float sc = gamma[o] * rsqrtf(var[o] + 1e-5f);
        float sh = beta[o] - mean[o] * sc;
        float* dst = g_w1 + (size_t)(b * CR + o) * HW + px0 + tx * 2;
        float v0 = fmaf(acc[i][0], sc, sh);
        float v1 = fmaf(acc[i][1], sc, sh);
        dst[0] = fmaxf(v0, 0.f);
        dst[1] = fmaxf(v1, 0.f);
    }
}

// ---------------------------------------------------------------------------
// K2: w2 = conv2_1x1(w1) + bias.  GEMM [784 x 64] x [64 x 3136] per batch.
// Tile 64o x 64px, 256 threads, 4x4 per thread, K=64 single shot.
// Grid: 49 x 13 x 4 = 2548 blocks.
// ---------------------------------------------------------------------------
__global__ __launch_bounds__(256) void k2_conv2(
        const float* __restrict__ w2w,
        const float* __restrict__ w2b) {
    __shared__ float As[64 * 68];    // [k][o]
    __shared__ float Bs[64 * 64];    // [k][px]

    const int tid = threadIdx.x;
    const int tx = tid & 15;         // px quad
    const int ty = tid >> 4;         // o quad
    const int px0 = blockIdx.x * 64; // 49*64 = 3136 exact
    const int o0 = blockIdx.y * 64;  // 13 tiles, guard 784
    const int b = blockIdx.z;

#pragma unroll
    for (int r = 0; r < 16; ++r) {
        int idx = tid + r * 256;
        int o = idx >> 6, k = idx & 63;
        As[k * 68 + o] = (o0 + o < M2) ? w2w[(o0 + o) * CR + k] : 0.f;
    }
#pragma unroll
    for (int r = 0; r < 16; ++r) {
        int idx = tid + r * 256;
        int k = idx >> 6, j = idx & 63;
        Bs[k * 64 + j] = g_w1[(size_t)(b * CR + k) * HW + px0 + j];
    }
    __syncthreads();

    float acc[4][4];
#pragma unroll
    for (int i = 0; i < 4; ++i)
#pragma unroll
        for (int u = 0; u < 4; ++u) acc[i][u] = 0.f;

#pragma unroll 16
    for (int k = 0; k < 64; ++k) {
        float4 av = *(const float4*)&As[k * 68 + ty * 4];
        float4 bv = *(const float4*)&Bs[k * 64 + tx * 4];
        acc[0][0] = fmaf(av.x, bv.x, acc[0][0]);
        acc[0][1] = fmaf(av.x, bv.y, acc[0][1]);
        acc[0][2] = fmaf(av.x, bv.z, acc[0][2]);
        acc[0][3] = fmaf(av.x, bv.w, acc[0][3]);
        acc[1][0] = fmaf(av.y, bv.x, acc[1][0]);
        acc[1][1] = fmaf(av.y, bv.y, acc[1][1]);
        acc[1][2] = fmaf(av.y, bv.z, acc[1][2]);
        acc[1][3] = fmaf(av.y, bv.w, acc[1][3]);
        acc[2][0] = fmaf(av.z, bv.x, acc[2][0]);
        acc[2][1] = fmaf(av.z, bv.y, acc[2][1]);
        acc[2][2] = fmaf(av.z, bv.z, acc[2][2]);
        acc[2][3] = fmaf(av.z, bv.w, acc[2][3]);
        acc[3][0] = fmaf(av.w, bv.x, acc[3][0]);
        acc[3][1] = fmaf(av.w, bv.y, acc[3][1]);
        acc[3][2] = fmaf(av.w, bv.z, acc[3][2]);
        acc[3][3] = fmaf(av.w, bv.w, acc[3][3]);
    }

#pragma unroll
    for (int i = 0; i < 4; ++i) {
        int o = o0 + ty * 4 + i;
        if (o >= M2) continue;
        float bias = w2b[o];
        float4 v;
        v.x = acc[i][0] + bias;
        v.y = acc[i][1] + bias;
        v.z = acc[i][2] + bias;
        v.w = acc[i][3] + bias;
        *(float4*)(g_w2 + (size_t)(b * M2 + o) * HW + px0 + tx * 4) = v;
    }
}

// ---------------------------------------------------------------------------
// K3: involution reduce. Block = (band of 2 rows, group, batch); 448 threads.
// Thread = 1 channel x 4 consecutive px. x staged in smem with +3 col shift
// so all windows are float4-aligned, zero boundary branches in the hot loop.
// ---------------------------------------------------------------------------
__global__ __launch_bounds__(448) void k3_involution(
        const float* __restrict__ x,
        float* __restrict__ out) {
    __shared__ float xs[GC * 8 * 64];   // [ch][row 0..7][col(+3 shift) 0..63] 32KB

    const int tid = threadIdx.x;
    const int h0 = blockIdx.x * 2;      // output row band
    const int g = blockIdx.y;
    const int b = blockIdx.z;

    // cooperative x staging: rows h0-3 .. h0+4, cols -3 .. 60 (clipped -> 0)
    const float* xg = x + (size_t)(b * CC + g * GC) * HW;
#pragma unroll
    for (int i = tid; i < GC * 8 * 64; i += 448) {
        int ch = i >> 9;
        int rr = (i >> 6) & 7;
        int c = i & 63;
        int hh = h0 - 3 + rr;
        int ww = c - 3;
        float v = 0.f;
        if (hh >= 0 && hh < HH && ww >= 0 && ww < WW)
            v = xg[(size_t)ch * HW + hh * WW + ww];
        xs[i] = v;
    }
    __syncthreads();

    // thread mapping: ch = tid/28, r = (tid%28)/14, q = tid%14
    const int ch = tid / 28;
    const int rq = tid % 28;
    const int r = rq / 14;
    const int q = rq % 14;
    const int w0 = q * 4;
    const int h = h0 + r;

    const float* wg = g_w2 + ((size_t)(b * GG + g) * K2T) * HW + h * WW + w0;
    float4 acc = make_float4(0.f, 0.f, 0.f, 0.f);

#pragma unroll
    for (int ki = 0; ki < KK; ++ki) {
        const float* xr = &xs[ch * 512 + (r + ki) * 64 + w0];
        float4 xa = *(const float4*)(xr);
        float4 xb = *(const float4*)(xr + 4);
        float4 xc = *(const float4*)(xr + 8);
        float xw[12] = {xa.x, xa.y, xa.z, xa.w,
                        xb.x, xb.y, xb.z, xb.w,
                        xc.x, xc.y, xc.z, xc.w};
        const float* wp = wg + (size_t)(ki * KK) * HW;
#pragma unroll
        for (int kj = 0; kj < KK; ++kj) {
            float4 wv = *(const float4*)(wp + (size_t)kj * HW);
            acc.x = fmaf(wv.x, xw[kj + 0], acc.x);
            acc.y = fmaf(wv.y, xw[kj + 1], acc.y);
            acc.z = fmaf(wv.z, xw[kj + 2], acc.z);
            acc.w = fmaf(wv.w, xw[kj + 3], acc.w);
        }
    }

    *(float4*)(out + (size_t)(b * CC + g * GC + ch) * HW + h * WW + w0) = acc;
}

// ---------------------------------------------------------------------------
extern "C" void kernel_launch(void* const* d_in, const int* in_sizes, int n_in,
                              void* d_out, int out_size) {
    const float* x     = (const float*)d_in[0];
    const float* w1w   = (const float*)d_in[1];
    const float* gamma = (const float*)d_in[2];
    const float* beta  = (const float*)d_in[3];
    const float* mean  = (const float*)d_in[4];
    const float* var   = (const float*)d_in[5];
    const float* w2w   = (const float*)d_in[6];
    const float* w2b   = (const float*)d_in[7];
    float* out = (float*)d_out;

    dim3 g1(HW / 32, BB);                       // 98 x 4 = 392
    k1_conv1_bn_relu<<<g1, 256>>>(x, w1w, gamma, beta, mean, var);

    dim3 g2(HW / 64, (M2 + 63) / 64, BB);       // 49 x 13 x 4 = 2548
    k2_conv2<<<g2, 256>>>(w2w, w2b);

    dim3 g3(HH / 2, GG, BB);                    // 28 x 16 x 4 = 1792
    k3_involution<<<g3, 448>>>(x, out);
}

// round 4
// speedup vs baseline: 1.1705x; 1.1705x over previous
#include <cuda_runtime.h>

#define BB 4
#define CC 256
#define HH 56
#define WW 56
#define CR 64          // C / 4
#define GG 16          // groups
#define GC 16
#define KK 7
#define K2T 49
#define M2 784         // GG * K2T
#define HW 3136        // HH * WW
#define PAD 3

// Scratch (__device__ globals; no allocations allowed)
__device__ float g_w1[BB * CR * HW];        // [B, Cr, HW]
__device__ float g_w2[BB * M2 * HW];        // [B, G*49, HW]

// ---------------------------------------------------------------------------
// K1: w1 = relu(bn(conv1_1x1(x))).  GEMM [64 x 256] x [256 x 3136] per batch.
// Tile 64o x 32px, 64 threads, 8x4 per thread, k-step 64, A transposed [k][o].
// Grid: 98 x 4 = 392 blocks of 2 warps (many resident per SM).
// ---------------------------------------------------------------------------
__global__ __launch_bounds__(64) void k1_conv1_bn_relu(
        const float* __restrict__ x,
        const float* __restrict__ w1w,
        const float* __restrict__ gamma,
        const float* __restrict__ beta,
        const float* __restrict__ mean,
        const float* __restrict__ var) {
    __shared__ float As[64 * 68];    // [k][o], stride 68 (272B, 16B-aligned)
    __shared__ float Bs[64 * 32];    // [k][px]

    const int tid = threadIdx.x;
    const int tx = tid & 7;          // px quad  (8 quads  = 32 px)
    const int ty = tid >> 3;         // o octet  (8 octets = 64 o)
    const int px0 = blockIdx.x * 32; // 98*32 = 3136 exact
    const int b = blockIdx.y;

    float acc[8][4];
#pragma unroll
    for (int i = 0; i < 8; ++i)
#pragma unroll
        for (int u = 0; u < 4; ++u) acc[i][u] = 0.f;

    for (int kt = 0; kt < CC; kt += 64) {
        // As: o = r, k = tid  (coalesced LDG, transposed STS)
#pragma unroll
        for (int r = 0; r < 64; ++r)
            As[tid * 68 + r] = w1w[r * CC + kt + tid];
        // Bs: 2048 floats, k = 2r + (tid>>5), j = tid&31
#pragma unroll
        for (int r = 0; r < 32; ++r) {
            int k = 2 * r + (tid >> 5);
            int j = tid & 31;
            Bs[k * 32 + j] = x[(size_t)(b * CC + kt + k) * HW + px0 + j];
        }
        __syncthreads();

#pragma unroll 8
        for (int k = 0; k < 64; ++k) {
            float4 a0 = *(const float4*)&As[k * 68 + ty * 8];
            float4 a1 = *(const float4*)&As[k * 68 + ty * 8 + 4];
            float4 bv = *(const float4*)&Bs[k * 32 + tx * 4];
            float av[8] = {a0.x, a0.y, a0.z, a0.w, a1.x, a1.y, a1.z, a1.w};
#pragma unroll
            for (int i = 0; i < 8; ++i) {
                acc[i][0] = fmaf(av[i], bv.x, acc[i][0]);
                acc[i][1] = fmaf(av[i], bv.y, acc[i][1]);
                acc[i][2] = fmaf(av[i], bv.z, acc[i][2]);
                acc[i][3] = fmaf(av[i], bv.w, acc[i][3]);
            }
        }
        __syncthreads();
    }

#pragma unroll
    for (int i = 0; i < 8; ++i) {
        int o = ty * 8 + i;
        float sc = gamma[o] * rsqrtf(var[o] + 1e-5f);
        float sh = beta[o] - mean[o] * sc;
        float4 v;
        v.x = fmaxf(fmaf(acc[i][0], sc, sh), 0.f);
        v.y = fmaxf(fmaf(acc[i][1], sc, sh), 0.f);
        v.z = fmaxf(fmaf(acc[i][2], sc, sh), 0.f);
        v.w = fmaxf(fmaf(acc[i][3], sc, sh), 0.f);
        *(float4*)(g_w1 + (size_t)(b * CR + o) * HW + px0 + tx * 4) = v;
    }
}

// ---------------------------------------------------------------------------
// K2: w2 = conv2_1x1(w1) + bias.  GEMM [784 x 64] x [64 x 3136] per batch.
// Tile 64o x 64px, 64 threads, 8x8 per thread, K=64 one shot.
// Grid: 49 x 13 x 4 = 2548 blocks of 2 warps.
// ---------------------------------------------------------------------------
__global__ __launch_bounds__(64) void k2_conv2(
        const float* __restrict__ w2w,
        const float* __restrict__ w2b) {
    __shared__ float As[64 * 68];    // [k][o]
    __shared__ float Bs[64 * 64];    // [k][px]

    const int tid = threadIdx.x;
    const int tx = tid & 7;          // px octet
    const int ty = tid >> 3;         // o octet
    const int px0 = blockIdx.x * 64; // 49*64 = 3136 exact
    const int o0 = blockIdx.y * 64;  // 13 tiles (832), guard at 784
    const int b = blockIdx.z;

    // As: o = r, k = tid (guarded), transposed store
#pragma unroll
    for (int r = 0; r < 64; ++r)
        As[tid * 68 + r] = (o0 + r < M2) ? w2w[(o0 + r) * CR + tid] : 0.f;
    // Bs: k = r, px = tid
#pragma unroll
    for (int r = 0; r < 64; ++r)
        Bs[r * 64 + tid] = g_w1[(size_t)(b * CR + r) * HW + px0 + tid];
    __syncthreads();

    float acc[8][8];
#pragma unroll
    for (int i = 0; i < 8; ++i)
#pragma unroll
        for (int u = 0; u < 8; ++u) acc[i][u] = 0.f;

#pragma unroll 4
    for (int k = 0; k < 64; ++k) {
        float4 a0 = *(const float4*)&As[k * 68 + ty * 8];
        float4 a1 = *(const float4*)&As[k * 68 + ty * 8 + 4];
        float4 b0 = *(const float4*)&Bs[k * 64 + tx * 8];
        float4 b1 = *(const float4*)&Bs[k * 64 + tx * 8 + 4];
        float av[8] = {a0.x, a0.y, a0.z, a0.w, a1.x, a1.y, a1.z, a1.w};
        float bv[8] = {b0.x, b0.y, b0.z, b0.w, b1.x, b1.y, b1.z, b1.w};
#pragma unroll
        for (int i = 0; i < 8; ++i)
#pragma unroll
            for (int u = 0; u < 8; ++u)
                acc[i][u] = fmaf(av[i], bv[u], acc[i][u]);
    }

#pragma unroll
    for (int i = 0; i < 8; ++i) {
        int o = o0 + ty * 8 + i;
        if (o >= M2) continue;
        float bias = w2b[o];
        float* dst = g_w2 + (size_t)(b * M2 + o) * HW + px0 + tx * 8;
        float4 v0, v1;
        v0.x = acc[i][0] + bias; v0.y = acc[i][1] + bias;
        v0.z = acc[i][2] + bias; v0.w = acc[i][3] + bias;
        v1.x = acc[i][4] + bias; v1.y = acc[i][5] + bias;
        v1.z = acc[i][6] + bias; v1.w = acc[i][7] + bias;
        *(float4*)dst = v0;
        *(float4*)(dst + 4) = v1;
    }
}

// ---------------------------------------------------------------------------
// K3: involution reduce. Block = (4-row band, group, batch); 224 threads.
// Thread = 4 px x 4 ch: each weight LDG.128 feeds 16 FMAs (4x less weight
// traffic than 1-ch threads). x staged in smem with +3 shift (no branches).
// ---------------------------------------------------------------------------
__global__ __launch_bounds__(224) void k3_involution(
        const float* __restrict__ x,
        float* __restrict__ out) {
    __shared__ float xs[GC * 10 * 64];   // [ch][row 0..9][col(+3) 0..63] 40KB

    const int tid = threadIdx.x;
    const int h0 = blockIdx.x * 4;       // output row band (14 bands)
    const int g = blockIdx.y;
    const int b = blockIdx.z;

    // stage x: rows h0-3 .. h0+6, cols -3..60 (clipped)
    const float* xg = x + (size_t)(b * CC + g * GC) * HW;
    for (int i = tid; i < GC * 10 * 64; i += 224) {
        int ch = i / 640;
        int rem = i - ch * 640;
        int rr = rem >> 6;
        int c = rem & 63;
        int hh = h0 - 3 + rr;
        int ww = c - 3;
        float v = 0.f;
        if (hh >= 0 && hh < HH && ww >= 0 && ww < WW)
            v = xg[(size_t)ch * HW + hh * WW + ww];
        xs[i] = v;
    }
    __syncthreads();

    // mapping: q (px quad, 14) fastest, then cg (ch group, 4), then r (row, 4)
    const int q = tid % 14;
    const int cg = (tid / 14) & 3;
    const int r = tid / 56;
    const int w0 = q * 4;
    const int h = h0 + r;

    const float* wg = g_w2 + ((size_t)(b * GG + g) * K2T) * HW + h * WW + w0;

    float acc[4][4];
#pragma unroll
    for (int c = 0; c < 4; ++c)
#pragma unroll
        for (int p = 0; p < 4; ++p) acc[c][p] = 0.f;

#pragma unroll
    for (int ki = 0; ki < KK; ++ki) {
        float4 wv[7];
#pragma unroll
        for (int kj = 0; kj < KK; ++kj)
            wv[kj] = *(const float4*)(wg + (size_t)(ki * KK + kj) * HW);
#pragma unroll
        for (int c = 0; c < 4; ++c) {
            const float* xr = &xs[(cg * 4 + c) * 640 + (r + ki) * 64 + w0];
            float4 xa = *(const float4*)(xr);
            float4 xb = *(const float4*)(xr + 4);
            float4 xc = *(const float4*)(xr + 8);
            float xw[12] = {xa.x, xa.y, xa.z, xa.w,
                            xb.x, xb.y, xb.z, xb.w,
                            xc.x, xc.y, xc.z, xc.w};
#pragma unroll
            for (int kj = 0; kj < KK; ++kj) {
                acc[c][0] = fmaf(wv[kj].x, xw[kj + 0], acc[c][0]);
                acc[c][1] = fmaf(wv[kj].y, xw[kj + 1], acc[c][1]);
                acc[c][2] = fmaf(wv[kj].z, xw[kj + 2], acc[c][2]);
                acc[c][3] = fmaf(wv[kj].w, xw[kj + 3], acc[c][3]);
            }
        }
    }

#pragma unroll
    for (int c = 0; c < 4; ++c) {
        float4 v = make_float4(acc[c][0], acc[c][1], acc[c][2], acc[c][3]);
        *(float4*)(out + (size_t)(b * CC + g * GC + cg * 4 + c) * HW
                   + h * WW + w0) = v;
    }
}

// ---------------------------------------------------------------------------
extern "C" void kernel_launch(void* const* d_in, const int* in_sizes, int n_in,
                              void* d_out, int out_size) {
    const float* x     = (const float*)d_in[0];
    const float* w1w   = (const float*)d_in[1];
    const float* gamma = (const float*)d_in[2];
    const float* beta  = (const float*)d_in[3];
    const float* mean  = (const float*)d_in[4];
    const float* var   = (const float*)d_in[5];
    const float* w2w   = (const float*)d_in[6];
    const float* w2b   = (const float*)d_in[7];
    float* out = (float*)d_out;

    dim3 g1(HW / 32, BB);                       // 98 x 4 = 392
    k1_conv1_bn_relu<<<g1, 64>>>(x, w1w, gamma, beta, mean, var);

    dim3 g2(HW / 64, (M2 + 63) / 64, BB);       // 49 x 13 x 4 = 2548
    k2_conv2<<<g2, 64>>>(w2w, w2b);

    dim3 g3(HH / 4, GG, BB);                    // 14 x 16 x 4 = 896
    k3_involution<<<g3, 224>>>(x, out);
}